// round 2
// baseline (speedup 1.0000x reference)
#include <cuda_runtime.h>
#include <cstdint>

#define C_CH   128
#define HW     16384
#define BATCH  8
#define QKV_CH 384
#define NHEAD  8
#define DH     16
#define NCHUNK 16   // gram N-chunks per (b,head)

// packed f32x2 helpers (Blackwell FFMA2 — only reachable via PTX)
#define PACK2(d, x, y)   asm("mov.b64 %0, {%1,%2};" : "=l"(d) : "f"(x), "f"(y))
#define UNPACK2(x, y, d) asm("mov.b64 {%0,%1}, %2;" : "=f"(x), "=f"(y) : "l"(d))
#define FMA2(d, a, b)    asm("fma.rn.f32x2 %0, %1, %2, %0;" : "+l"(d) : "l"(a), "l"(b))

// ---------------- scratch (static device globals; no runtime allocation) ----
__device__ float g_qkv  [(long)BATCH * QKV_CH * HW];   // after 1x1 qkv conv
__device__ float g_qkv2 [(long)BATCH * QKV_CH * HW];   // after depthwise 3x3
__device__ float g_part [64 * NCHUNK * 288];           // gram partials + norm partials
__device__ float g_attn [64 * 256];                    // softmaxed 16x16 per (b,head)
__device__ float g_ctx  [(long)BATCH * C_CH * HW];     // attention output

// ---------------- SGEMM: C[z][m][n] = sum_k A[m][k] * B[z][k][n] -------------
// K = 128 fixed, N = 16384 fixed. M = gridDim.y * 128. fp32 with packed
// fma.rn.f32x2 inner loop (FFMA2, full 128 MAC/cyc/SM rate).
__global__ void __launch_bounds__(256) sgemm_k128(
    const float* __restrict__ A,    // [M,128] row-major
    const float* __restrict__ Bg,   // [batch][128][16384]
    float* __restrict__ Cg)         // [batch][M][16384]
{
    const int K = 128, N = HW;
    const float* B = Bg + (long)blockIdx.z * K * N;
    float*       C = Cg + (long)blockIdx.z * (long)gridDim.y * 128 * N;

    const int m0 = blockIdx.y * 128;
    const int n0 = blockIdx.x * 128;

    __shared__ float As[8][132];   // padded; 132 floats = 528B keeps 16B alignment per row
    __shared__ float Bs[8][128];

    const int tid = threadIdx.x;
    const int tx  = tid & 15;      // n-subtile
    const int ty  = tid >> 4;      // m-subtile

    // global load mapping
    const int arow = tid >> 1;          // 0..127 (m within tile)
    const int acol = (tid & 1) * 4;     // 0 or 4 (k within slab)
    const int brow = tid >> 5;          // 0..7   (k within slab)
    const int bcol = (tid & 31) * 4;    // 0..124 (n within tile)

    const float* Aptr = A + (long)(m0 + arow) * K + acol;
    const float* Bptr = B + (long)brow * N + n0 + bcol;

    // packed accumulators: acc2[i][jp] holds C[m+i][n + 2*jp .. 2*jp+1]
    uint64_t acc2[8][4];
    #pragma unroll
    for (int i = 0; i < 8; i++)
        #pragma unroll
        for (int jp = 0; jp < 4; jp++) acc2[i][jp] = 0ull;

    float4 av = *(const float4*)(Aptr);
    float4 bv = *(const float4*)(Bptr);

    for (int k0 = 0; k0 < K; k0 += 8) {
        As[acol + 0][arow] = av.x;
        As[acol + 1][arow] = av.y;
        As[acol + 2][arow] = av.z;
        As[acol + 3][arow] = av.w;
        *(float4*)&Bs[brow][bcol] = bv;
        __syncthreads();

        if (k0 + 8 < K) {
            av = *(const float4*)(Aptr + k0 + 8);
            bv = *(const float4*)(Bptr + (long)(k0 + 8) * N);
        }

        #pragma unroll
        for (int kk = 0; kk < 8; kk++) {
            float4 a01 = *(const float4*)&As[kk][ty * 8];
            float4 a23 = *(const float4*)&As[kk][ty * 8 + 4];
            float4 b01 = *(const float4*)&Bs[kk][tx * 8];
            float4 b23 = *(const float4*)&Bs[kk][tx * 8 + 4];

            uint64_t b2[4];
            PACK2(b2[0], b01.x, b01.y);
            PACK2(b2[1], b01.z, b01.w);
            PACK2(b2[2], b23.x, b23.y);
            PACK2(b2[3], b23.z, b23.w);

            uint64_t ad[8];
            PACK2(ad[0], a01.x, a01.x);
            PACK2(ad[1], a01.y, a01.y);
            PACK2(ad[2], a01.z, a01.z);
            PACK2(ad[3], a01.w, a01.w);
            PACK2(ad[4], a23.x, a23.x);
            PACK2(ad[5], a23.y, a23.y);
            PACK2(ad[6], a23.z, a23.z);
            PACK2(ad[7], a23.w, a23.w);

            #pragma unroll
            for (int i = 0; i < 8; i++)
                #pragma unroll
                for (int jp = 0; jp < 4; jp++)
                    FMA2(acc2[i][jp], ad[i], b2[jp]);
        }
        __syncthreads();
    }

    #pragma unroll
    for (int i = 0; i < 8; i++) {
        float4 c0, c1;
        UNPACK2(c0.x, c0.y, acc2[i][0]);
        UNPACK2(c0.z, c0.w, acc2[i][1]);
        UNPACK2(c1.x, c1.y, acc2[i][2]);
        UNPACK2(c1.z, c1.w, acc2[i][3]);
        float* crow = C + (long)(m0 + ty * 8 + i) * N + n0 + tx * 8;
        *(float4*)(crow)     = c0;
        *(float4*)(crow + 4) = c1;
    }
}

// ---------------- depthwise 3x3, SAME padding, per-channel weights ----------
__global__ void __launch_bounds__(256) dwconv3x3(
    const float* __restrict__ in,   // [B*384][128][128]
    const float* __restrict__ w,    // [384][1][3][3]
    float* __restrict__ out)
{
    const int n  = blockIdx.x * 256 + threadIdx.x;   // 0..16383
    const int bc = blockIdx.y;                        // 0..3071
    const int ch = bc % QKV_CH;
    const int y  = n >> 7;
    const int x  = n & 127;

    const float* ip = in + (long)bc * HW;
    const float* wp = w + ch * 9;

    float s = 0.f;
    #pragma unroll
    for (int dy = -1; dy <= 1; dy++) {
        const int yy = y + dy;
        if (yy < 0 || yy > 127) continue;
        #pragma unroll
        for (int dx = -1; dx <= 1; dx++) {
            const int xx = x + dx;
            if (xx < 0 || xx > 127) continue;
            s += ip[yy * 128 + xx] * wp[(dy + 1) * 3 + (dx + 1)];
        }
    }
    out[(long)bc * HW + n] = s;
}

// ---------------- gram partials: S[i][j] = sum_n q[i][n]k[j][n], + norms ----
// grid (NCHUNK, 64). Each block: one (b,head), one 1024-wide N chunk.
__global__ void __launch_bounds__(256) gram16(
    const float* __restrict__ qkv2, float* __restrict__ partials)
{
    const int bh = blockIdx.y;
    const int b  = bh >> 3, hd = bh & 7;
    const int n0 = blockIdx.x * 1024;

    const float* qg = qkv2 + (long)b * QKV_CH * HW + (long)hd * DH * HW + n0;
    const float* kg = qg + (long)C_CH * HW;

    __shared__ float qs[16 * 129];
    __shared__ float ks[16 * 129];

    const int tid = threadIdx.x;
    const int i = tid >> 4, j = tid & 15;

    float acc = 0.f, nacc = 0.f;

    for (int t0 = 0; t0 < 1024; t0 += 128) {
        #pragma unroll
        for (int idx = tid; idx < 2048; idx += 256) {
            const int r = idx >> 7, c = idx & 127;
            qs[r * 129 + c] = qg[(long)r * HW + t0 + c];
            ks[r * 129 + c] = kg[(long)r * HW + t0 + c];
        }
        __syncthreads();
        #pragma unroll 8
        for (int t = 0; t < 128; t++)
            acc += qs[i * 129 + t] * ks[j * 129 + t];
        if (tid < 16) {
            #pragma unroll 8
            for (int t = 0; t < 128; t++) { float v = qs[tid * 129 + t]; nacc += v * v; }
        } else if (tid < 32) {
            #pragma unroll 8
            for (int t = 0; t < 128; t++) { float v = ks[(tid - 16) * 129 + t]; nacc += v * v; }
        }
        __syncthreads();
    }

    float* p = partials + ((long)bh * NCHUNK + blockIdx.x) * 288;
    p[tid] = acc;
    if (tid < 32) p[256 + tid] = nacc;
}

// ---------------- reduce partials + normalize + temperature + softmax -------
__global__ void __launch_bounds__(256) attn_softmax(
    const float* __restrict__ partials,
    const float* __restrict__ temperature,
    float* __restrict__ attn)
{
    const int bh = blockIdx.x;
    const int hd = bh & 7;
    __shared__ float S[256];
    __shared__ float qn[16], kn[16];

    const int tid = threadIdx.x;
    float s = 0.f;
    #pragma unroll
    for (int c = 0; c < NCHUNK; c++)
        s += partials[((long)bh * NCHUNK + c) * 288 + tid];
    S[tid] = s;

    if (tid < 32) {
        float ns = 0.f;
        #pragma unroll
        for (int c = 0; c < NCHUNK; c++)
            ns += partials[((long)bh * NCHUNK + c) * 288 + 256 + tid];
        const float nv = fmaxf(sqrtf(ns), 1e-12f);
        if (tid < 16) qn[tid] = nv; else kn[tid - 16] = nv;
    }
    __syncthreads();

    if (tid < 16) {
        const int   i  = tid;
        const float tp = temperature[hd];
        float lg[16];
        float mx = -1e30f;
        #pragma unroll
        for (int j = 0; j < 16; j++) {
            lg[j] = S[i * 16 + j] / (qn[i] * kn[j]) * tp;
            mx = fmaxf(mx, lg[j]);
        }
        float sum = 0.f;
        #pragma unroll
        for (int j = 0; j < 16; j++) { lg[j] = expf(lg[j] - mx); sum += lg[j]; }
        const float inv = 1.f / sum;
        #pragma unroll
        for (int j = 0; j < 16; j++)
            attn[(long)bh * 256 + i * 16 + j] = lg[j] * inv;
    }
}

// ---------------- ctx[i][n] = sum_j attn[i][j] * v[j][n] * illu[j][n] -------
__global__ void __launch_bounds__(256) attn_apply(
    const float* __restrict__ qkv2,
    const float* __restrict__ illu,
    const float* __restrict__ attn,
    float* __restrict__ ctx)
{
    const int bh = blockIdx.y;
    const int b  = bh >> 3, hd = bh & 7;

    __shared__ float a[256];
    a[threadIdx.x] = attn[(long)bh * 256 + threadIdx.x];
    __syncthreads();

    const int n = blockIdx.x * 256 + threadIdx.x;
    const float* v  = qkv2 + (long)b * QKV_CH * HW + (long)(2 * C_CH + hd * DH) * HW + n;
    const float* il = illu + (long)b * C_CH   * HW + (long)(hd * DH) * HW + n;

    float vv[16];
    #pragma unroll
    for (int j = 0; j < 16; j++)
        vv[j] = v[(long)j * HW] * il[(long)j * HW];

    float* o = ctx + (long)b * C_CH * HW + (long)(hd * DH) * HW + n;
    #pragma unroll
    for (int i = 0; i < 16; i++) {
        float s = 0.f;
        #pragma unroll
        for (int j = 0; j < 16; j++)
            s += a[i * 16 + j] * vv[j];
        o[(long)i * HW] = s;
    }
}

// ---------------- launch --------------------------------------------------
extern "C" void kernel_launch(void* const* d_in, const int* in_sizes, int n_in,
                              void* d_out, int out_size)
{
    const float* x_in   = (const float*)d_in[0];
    const float* illu   = (const float*)d_in[1];
    const float* w_qkv  = (const float*)d_in[2];
    const float* w_dw   = (const float*)d_in[3];
    const float* w_proj = (const float*)d_in[4];
    const float* temp   = (const float*)d_in[5];
    float* out = (float*)d_out;

    float *qkv, *qkv2, *part, *attn, *ctx;
    cudaGetSymbolAddress((void**)&qkv,  g_qkv);
    cudaGetSymbolAddress((void**)&qkv2, g_qkv2);
    cudaGetSymbolAddress((void**)&part, g_part);
    cudaGetSymbolAddress((void**)&attn, g_attn);
    cudaGetSymbolAddress((void**)&ctx,  g_ctx);

    // 1) qkv = w_qkv @ x   (per batch: M=384, K=128, N=16384)
    sgemm_k128<<<dim3(HW / 128, QKV_CH / 128, BATCH), 256>>>(w_qkv, x_in, qkv);
    // 2) depthwise 3x3 SAME
    dwconv3x3<<<dim3(HW / 256, BATCH * QKV_CH), 256>>>(qkv, w_dw, qkv2);
    // 3) gram partials + norms
    gram16<<<dim3(NCHUNK, 64), 256>>>(qkv2, part);
    // 4) softmax(16x16) with l2-normalization and temperature
    attn_softmax<<<64, 256>>>(part, temp, attn);
    // 5) out = attn @ (v * illu)
    attn_apply<<<dim3(HW / 256, 64), 256>>>(qkv2, illu, attn, ctx);
    // 6) project_out (per batch: M=128, K=128, N=16384)
    sgemm_k128<<<dim3(HW / 128, C_CH / 128, BATCH), 256>>>(w_proj, ctx, out);
}

// round 4
// speedup vs baseline: 1.4711x; 1.4711x over previous
#include <cuda_runtime.h>
#include <cuda_bf16.h>
#include <cstdint>

#define C_CH   128
#define HW     16384
#define BATCH  8
#define QKV_CH 384
#define NHEAD  8
#define DH     16
#define NCHUNK 16

// ===================== scratch ==============================================
__device__ float g_qkv  [(long)BATCH * QKV_CH * HW];
__device__ float g_qkv2 [(long)BATCH * QKV_CH * HW];
__device__ float g_part [64 * NCHUNK * 288];
__device__ float g_attn [64 * 256];
__device__ float g_ctx  [(long)BATCH * C_CH * HW];

// ===================== warp-MMA helpers =====================================
__device__ __forceinline__ uint32_t smem_u32(const void* p) {
    uint32_t a;
    asm("{ .reg .u64 t; cvta.to.shared.u64 t, %1; cvt.u32.u64 %0, t; }" : "=r"(a) : "l"(p));
    return a;
}
__device__ __forceinline__ void ldsm_x4(uint32_t* r, uint32_t addr) {
    asm volatile("ldmatrix.sync.aligned.m8n8.x4.shared.b16 {%0,%1,%2,%3}, [%4];"
                 : "=r"(r[0]), "=r"(r[1]), "=r"(r[2]), "=r"(r[3]) : "r"(addr));
}
__device__ __forceinline__ void ldsm_x4_t(uint32_t* r, uint32_t addr) {
    asm volatile("ldmatrix.sync.aligned.m8n8.x4.trans.shared.b16 {%0,%1,%2,%3}, [%4];"
                 : "=r"(r[0]), "=r"(r[1]), "=r"(r[2]), "=r"(r[3]) : "r"(addr));
}
__device__ __forceinline__ void mma_bf16(float* d, const uint32_t* a, const uint32_t* b) {
    asm volatile(
        "mma.sync.aligned.m16n8k16.row.col.f32.bf16.bf16.f32 "
        "{%0,%1,%2,%3}, {%4,%5,%6,%7}, {%8,%9}, {%0,%1,%2,%3};"
        : "+f"(d[0]), "+f"(d[1]), "+f"(d[2]), "+f"(d[3])
        : "r"(a[0]), "r"(a[1]), "r"(a[2]), "r"(a[3]), "r"(b[0]), "r"(b[1]));
}

// ===================== tensor-core GEMM (mma.sync bf16 x3) ===================
// C[z][o][n] = sum_c W[o][c] * X[z][c][n]
// Block: 128(o) x 128(n), K = 128 in two 64-chunks through SMEM.
// 8 warps: 2(m) x 4(n), warp tile 64 x 32. bf16 split: hh + hl + lh, fp32 acc.
#define SA 72     // W tile k-stride (bf16 elems): 144B rows, conflict-free
#define SB 136    // X tile n-stride (bf16 elems): 272B rows, conflict-free
#define OFF_WHI 0
#define OFF_WLO (128 * SA * 2)
#define OFF_XHI (2 * 128 * SA * 2)
#define OFF_XLO (2 * 128 * SA * 2 + 64 * SB * 2)
#define SM_GEMM (2 * 128 * SA * 2 + 2 * 64 * SB * 2)   // 71680 B

__global__ void __launch_bounds__(256, 2) gemm_tc(
    const float* __restrict__ Wt,   // [Mw, 128] row-major
    const float* __restrict__ Xg,   // [batch][128][HW]
    float* __restrict__ Cg,         // [batch][Mw][HW]
    int Mw)
{
    extern __shared__ char sm[];
    const uint32_t smb = smem_u32(sm);

    const int tid  = threadIdx.x;
    const int lane = tid & 31;
    const int wid  = tid >> 5;
    const int wm   = wid >> 2;        // 0..1  (m offset 64*wm)
    const int wn   = wid & 3;         // 0..3  (n offset 32*wn)

    const int n0 = blockIdx.x * 128;
    const int m0 = blockIdx.y * 128;
    const float* X = Xg + (long)blockIdx.z * C_CH * HW;
    float*       C = Cg + (long)blockIdx.z * (long)Mw * HW;

    float acc[4][4][4];
    #pragma unroll
    for (int i = 0; i < 4; i++)
        #pragma unroll
        for (int j = 0; j < 4; j++)
            #pragma unroll
            for (int r = 0; r < 4; r++) acc[i][j][r] = 0.f;

    // ldmatrix per-lane address components
    // A (x4, row-major [m][k]): mat = lane/8; row = (lane&7) + 8*(mat&1); col = 8*(mat>>1)
    const int a_row = (lane & 7) + ((lane >> 3) & 1) * 8;
    const int a_col = (lane >> 4) * 8;
    // B (x4 trans, [k][n]): row = (lane&7) + 8*((lane>>3)&1) (k); col = 8*(lane>>4) (n)
    const int b_row = (lane & 7) + ((lane >> 3) & 1) * 8;
    const int b_col = (lane >> 4) * 8;

    for (int kc = 0; kc < 2; kc++) {
        __syncthreads();   // previous chunk's compute done before overwrite

        // ---- load + convert W chunk: [128 m][64 k] ----
        #pragma unroll
        for (int t = 0; t < 8; t++) {
            const int lin = t * 256 + tid;          // 0..2047
            const int row = lin >> 4;               // m 0..127
            const int c4  = lin & 15;               // k/4
            const float4 v = *(const float4*)&Wt[(long)(m0 + row) * 128 + kc * 64 + c4 * 4];
            __nv_bfloat16 h0 = __float2bfloat16(v.x), h1 = __float2bfloat16(v.y);
            __nv_bfloat16 h2 = __float2bfloat16(v.z), h3 = __float2bfloat16(v.w);
            __nv_bfloat16 l0 = __float2bfloat16(v.x - __bfloat162float(h0));
            __nv_bfloat16 l1 = __float2bfloat16(v.y - __bfloat162float(h1));
            __nv_bfloat16 l2 = __float2bfloat16(v.z - __bfloat162float(h2));
            __nv_bfloat16 l3 = __float2bfloat16(v.w - __bfloat162float(h3));
            __nv_bfloat162 hp0; hp0.x = h0; hp0.y = h1;
            __nv_bfloat162 hp1; hp1.x = h2; hp1.y = h3;
            __nv_bfloat162 lp0; lp0.x = l0; lp0.y = l1;
            __nv_bfloat162 lp1; lp1.x = l2; lp1.y = l3;
            uint2 hh = make_uint2(*(uint32_t*)&hp0, *(uint32_t*)&hp1);
            uint2 ll = make_uint2(*(uint32_t*)&lp0, *(uint32_t*)&lp1);
            *(uint2*)(sm + OFF_WHI + (row * SA + c4 * 4) * 2) = hh;
            *(uint2*)(sm + OFF_WLO + (row * SA + c4 * 4) * 2) = ll;
        }
        // ---- load + convert X chunk: [64 k][128 n] ----
        #pragma unroll
        for (int t = 0; t < 8; t++) {
            const int lin = t * 256 + tid;          // 0..2047
            const int row = lin >> 5;               // k 0..63
            const int n4  = lin & 31;               // n/4
            const float4 v = *(const float4*)&X[(long)(kc * 64 + row) * HW + n0 + n4 * 4];
            __nv_bfloat16 h0 = __float2bfloat16(v.x), h1 = __float2bfloat16(v.y);
            __nv_bfloat16 h2 = __float2bfloat16(v.z), h3 = __float2bfloat16(v.w);
            __nv_bfloat16 l0 = __float2bfloat16(v.x - __bfloat162float(h0));
            __nv_bfloat16 l1 = __float2bfloat16(v.y - __bfloat162float(h1));
            __nv_bfloat16 l2 = __float2bfloat16(v.z - __bfloat162float(h2));
            __nv_bfloat16 l3 = __float2bfloat16(v.w - __bfloat162float(h3));
            __nv_bfloat162 hp0; hp0.x = h0; hp0.y = h1;
            __nv_bfloat162 hp1; hp1.x = h2; hp1.y = h3;
            __nv_bfloat162 lp0; lp0.x = l0; lp0.y = l1;
            __nv_bfloat162 lp1; lp1.x = l2; lp1.y = l3;
            uint2 hh = make_uint2(*(uint32_t*)&hp0, *(uint32_t*)&hp1);
            uint2 ll = make_uint2(*(uint32_t*)&lp0, *(uint32_t*)&lp1);
            *(uint2*)(sm + OFF_XHI + (row * SB + n4 * 4) * 2) = hh;
            *(uint2*)(sm + OFF_XLO + (row * SB + n4 * 4) * 2) = ll;
        }
        __syncthreads();

        // ---- compute 4 k-steps of 16 ----
        #pragma unroll
        for (int ks = 0; ks < 4; ks++) {
            const int kk = ks * 16;
            uint32_t a[4][4], bh[2][4], bl[2][4];

            // B frags: x4 trans covers k16 x n16 (two n-frags)
            #pragma unroll
            for (int u = 0; u < 2; u++) {
                const int r = kk + b_row;
                const int c = wn * 32 + u * 16 + b_col;
                ldsm_x4_t(bh[u], smb + OFF_XHI + (r * SB + c) * 2);
                ldsm_x4_t(bl[u], smb + OFF_XLO + (r * SB + c) * 2);
            }
            // A hi frags: x4 covers m16 x k16
            #pragma unroll
            for (int i = 0; i < 4; i++) {
                const int r = wm * 64 + i * 16 + a_row;
                ldsm_x4(a[i], smb + OFF_WHI + (r * SA + kk + a_col) * 2);
            }
            // hh + hl
            #pragma unroll
            for (int i = 0; i < 4; i++)
                #pragma unroll
                for (int j = 0; j < 4; j++) {
                    mma_bf16(acc[i][j], a[i], &bh[j >> 1][(j & 1) * 2]);
                    mma_bf16(acc[i][j], a[i], &bl[j >> 1][(j & 1) * 2]);
                }
            // A lo frags overwrite a[]
            #pragma unroll
            for (int i = 0; i < 4; i++) {
                const int r = wm * 64 + i * 16 + a_row;
                ldsm_x4(a[i], smb + OFF_WLO + (r * SA + kk + a_col) * 2);
            }
            // lh
            #pragma unroll
            for (int i = 0; i < 4; i++)
                #pragma unroll
                for (int j = 0; j < 4; j++)
                    mma_bf16(acc[i][j], a[i], &bh[j >> 1][(j & 1) * 2]);
        }
    }

    // ---- epilogue: write D[m][n] -> C[o][n] ----
    const int mw = m0 + wm * 64;
    const int nw = n0 + wn * 32;
    #pragma unroll
    for (int i = 0; i < 4; i++) {
        #pragma unroll
        for (int j = 0; j < 4; j++) {
            const int row0 = mw + i * 16 + (lane >> 2);
            const int col  = nw + j * 8 + (lane & 3) * 2;
            *(float2*)&C[(long)row0 * HW + col]       = make_float2(acc[i][j][0], acc[i][j][1]);
            *(float2*)&C[(long)(row0 + 8) * HW + col] = make_float2(acc[i][j][2], acc[i][j][3]);
        }
    }
}

// ===================== depthwise 3x3 ========================================
__global__ void __launch_bounds__(256) dwconv3x3(
    const float* __restrict__ in, const float* __restrict__ w, float* __restrict__ out)
{
    const int n  = blockIdx.x * 256 + threadIdx.x;
    const int bc = blockIdx.y;
    const int ch = bc % QKV_CH;
    const int y  = n >> 7;
    const int x  = n & 127;
    const float* ip = in + (long)bc * HW;
    const float* wp = w + ch * 9;
    float s = 0.f;
    #pragma unroll
    for (int dy = -1; dy <= 1; dy++) {
        const int yy = y + dy;
        if (yy < 0 || yy > 127) continue;
        #pragma unroll
        for (int dx = -1; dx <= 1; dx++) {
            const int xx = x + dx;
            if (xx < 0 || xx > 127) continue;
            s += ip[yy * 128 + xx] * wp[(dy + 1) * 3 + (dx + 1)];
        }
    }
    out[(long)bc * HW + n] = s;
}

// ===================== gram partials ========================================
__global__ void __launch_bounds__(256) gram16(
    const float* __restrict__ qkv2, float* __restrict__ partials)
{
    const int bh = blockIdx.y;
    const int b  = bh >> 3, hd = bh & 7;
    const int n0 = blockIdx.x * 1024;
    const float* qg = qkv2 + (long)b * QKV_CH * HW + (long)hd * DH * HW + n0;
    const float* kg = qg + (long)C_CH * HW;

    __shared__ float qs[16 * 129];
    __shared__ float ks[16 * 129];
    const int tid = threadIdx.x;
    const int i = tid >> 4, j = tid & 15;
    float acc = 0.f, nacc = 0.f;

    for (int t0 = 0; t0 < 1024; t0 += 128) {
        #pragma unroll
        for (int idx = tid; idx < 2048; idx += 256) {
            const int r = idx >> 7, c = idx & 127;
            qs[r * 129 + c] = qg[(long)r * HW + t0 + c];
            ks[r * 129 + c] = kg[(long)r * HW + t0 + c];
        }
        __syncthreads();
        #pragma unroll 8
        for (int t = 0; t < 128; t++)
            acc += qs[i * 129 + t] * ks[j * 129 + t];
        if (tid < 16) {
            #pragma unroll 8
            for (int t = 0; t < 128; t++) { float v = qs[tid * 129 + t]; nacc += v * v; }
        } else if (tid < 32) {
            #pragma unroll 8
            for (int t = 0; t < 128; t++) { float v = ks[(tid - 16) * 129 + t]; nacc += v * v; }
        }
        __syncthreads();
    }
    float* p = partials + ((long)bh * NCHUNK + blockIdx.x) * 288;
    p[tid] = acc;
    if (tid < 32) p[256 + tid] = nacc;
}

// ===================== softmax ==============================================
__global__ void __launch_bounds__(256) attn_softmax(
    const float* __restrict__ partials, const float* __restrict__ temperature,
    float* __restrict__ attn)
{
    const int bh = blockIdx.x;
    const int hd = bh & 7;
    __shared__ float S[256];
    __shared__ float qn[16], kn[16];
    const int tid = threadIdx.x;
    float s = 0.f;
    #pragma unroll
    for (int c = 0; c < NCHUNK; c++)
        s += partials[((long)bh * NCHUNK + c) * 288 + tid];
    S[tid] = s;
    if (tid < 32) {
        float ns = 0.f;
        #pragma unroll
        for (int c = 0; c < NCHUNK; c++)
            ns += partials[((long)bh * NCHUNK + c) * 288 + 256 + tid];
        const float nv = fmaxf(sqrtf(ns), 1e-12f);
        if (tid < 16) qn[tid] = nv; else kn[tid - 16] = nv;
    }
    __syncthreads();
    if (tid < 16) {
        const int   i  = tid;
        const float tp = temperature[hd];
        float lg[16];
        float mx = -1e30f;
        #pragma unroll
        for (int j = 0; j < 16; j++) {
            lg[j] = S[i * 16 + j] / (qn[i] * kn[j]) * tp;
            mx = fmaxf(mx, lg[j]);
        }
        float sum = 0.f;
        #pragma unroll
        for (int j = 0; j < 16; j++) { lg[j] = expf(lg[j] - mx); sum += lg[j]; }
        const float inv = 1.f / sum;
        #pragma unroll
        for (int j = 0; j < 16; j++)
            attn[(long)bh * 256 + i * 16 + j] = lg[j] * inv;
    }
}

// ===================== attn apply ===========================================
__global__ void __launch_bounds__(256) attn_apply(
    const float* __restrict__ qkv2, const float* __restrict__ illu,
    const float* __restrict__ attn, float* __restrict__ ctx)
{
    const int bh = blockIdx.y;
    const int b  = bh >> 3, hd = bh & 7;
    __shared__ float a[256];
    a[threadIdx.x] = attn[(long)bh * 256 + threadIdx.x];
    __syncthreads();
    const int n = blockIdx.x * 256 + threadIdx.x;
    const float* v  = qkv2 + (long)b * QKV_CH * HW + (long)(2 * C_CH + hd * DH) * HW + n;
    const float* il = illu + (long)b * C_CH   * HW + (long)(hd * DH) * HW + n;
    float vv[16];
    #pragma unroll
    for (int j = 0; j < 16; j++)
        vv[j] = v[(long)j * HW] * il[(long)j * HW];
    float* o = ctx + (long)b * C_CH * HW + (long)(hd * DH) * HW + n;
    #pragma unroll
    for (int i = 0; i < 16; i++) {
        float s = 0.f;
        #pragma unroll
        for (int j = 0; j < 16; j++)
            s += a[i * 16 + j] * vv[j];
        o[(long)i * HW] = s;
    }
}

// ===================== launch ===============================================
extern "C" void kernel_launch(void* const* d_in, const int* in_sizes, int n_in,
                              void* d_out, int out_size)
{
    const float* x_in   = (const float*)d_in[0];
    const float* illu   = (const float*)d_in[1];
    const float* w_qkv  = (const float*)d_in[2];
    const float* w_dw   = (const float*)d_in[3];
    const float* w_proj = (const float*)d_in[4];
    const float* temp   = (const float*)d_in[5];
    float* out = (float*)d_out;

    float *qkv, *qkv2, *part, *attn, *ctx;
    cudaGetSymbolAddress((void**)&qkv,  g_qkv);
    cudaGetSymbolAddress((void**)&qkv2, g_qkv2);
    cudaGetSymbolAddress((void**)&part, g_part);
    cudaGetSymbolAddress((void**)&attn, g_attn);
    cudaGetSymbolAddress((void**)&ctx,  g_ctx);

    cudaFuncSetAttribute(gemm_tc, cudaFuncAttributeMaxDynamicSharedMemorySize, SM_GEMM);

    // 1) qkv = w_qkv @ x   (per batch: Mw=384, K=128, N=16384)
    gemm_tc<<<dim3(HW / 128, QKV_CH / 128, BATCH), 256, SM_GEMM>>>(w_qkv, x_in, qkv, QKV_CH);
    // 2) depthwise 3x3 SAME
    dwconv3x3<<<dim3(HW / 256, BATCH * QKV_CH), 256>>>(qkv, w_dw, qkv2);
    // 3) gram partials + norms
    gram16<<<dim3(NCHUNK, 64), 256>>>(qkv2, part);
    // 4) softmax(16x16) with l2-normalization and temperature
    attn_softmax<<<64, 256>>>(part, temp, attn);
    // 5) ctx = attn @ (v * illu)
    attn_apply<<<dim3(HW / 256, 64), 256>>>(qkv2, illu, attn, ctx);
    // 6) out = w_proj @ ctx (per batch: Mw=128)
    gemm_tc<<<dim3(HW / 128, C_CH / 128, BATCH), 256, SM_GEMM>>>(w_proj, ctx, out, C_CH);
}